// round 13
// baseline (speedup 1.0000x reference)
#include <cuda_runtime.h>

#define BB 8192
#define TT 2048
#define NTHREADS 128           // 4 warps/block -> 1 warp per SMSP
#define NBLOCKS  128           // 512 warps; lane pair per chain
#define CHUNK 8                // timesteps per prefetch chunk

__device__ __forceinline__ float tanh_ap(float x) {
    float y;
    asm("tanh.approx.f32 %0, %1;" : "=f"(y) : "f"(x));
    return y;
}

// Lane pair (2j,2j+1) owns one chain; lane parity u owns hidden unit u.
// DEFERRED-h FORM (R11): h = sigma(o)*tanh(c) never materialized; whO/whX
// pre-multiplied by sigma_o during the tanh(c) wait.
// R12 change: MUFU issue order i, g, f, o (o LAST). The c'-critical f-gate
// moves from issue slot 3 to slot 2 (-16 cyc of rt16 stagger off the path);
// o's result keeps ~44 cyc of slack before the weight prep needs it.
// Timeline (t=0 at tc): shfl 86 -> z 90 -> ti 150/si 154 -> tg 166/q0 170
// -> tf 182 -> c' 186  (was 202 with o-first).
__global__ void __launch_bounds__(NTHREADS, 1)
lstm_kernel(const float* __restrict__ x,
            const float* __restrict__ h0in,
            const float* __restrict__ c0in,
            const float* __restrict__ w_ih,
            const float* __restrict__ w_hh,
            const float* __restrict__ b_ih,
            const float* __restrict__ b_hh,
            float* __restrict__ out)
{
    const int tid  = blockIdx.x * NTHREADS + threadIdx.x;
    const int u    = tid & 1;           // hidden unit owned by this lane
    const int vv   = u ^ 1;             // partner's unit
    const int pair = tid >> 1;          // chain (batch element)

    // Gate order q: 0=i, 1=g, 2=f, 3=o (rows 0+u, 4+u, 2+u, 6+u).
    // sigma(z)=0.5*tanh(0.5z)+0.5 with 0.5 folded into weights/bias; g unscaled.
    float wi0[4], wi1[4], whO[4], whX[4], bs[4];
    const int qrow[4] = {0 + u, 4 + u, 2 + u, 6 + u};   // i, g, f, o
#pragma unroll
    for (int q = 0; q < 4; q++) {
        const int row = qrow[q];
        const float s = (q == 1) ? 1.0f : 0.5f;
        wi0[q] = s * __ldg(&w_ih[2*row+0]);
        wi1[q] = s * __ldg(&w_ih[2*row+1]);
        whO[q] = s * __ldg(&w_hh[2*row+u]);
        whX[q] = s * __ldg(&w_hh[2*row+vv]);
        bs[q]  = s * (__ldg(&b_ih[row]) + __ldg(&b_hh[row]));
    }

    float c  = c0in[2*pair + u];
    float hc = 0.5f * c;                // running 0.5*c (off critical path)

    // Deferred-h bootstrap: sigma_o := 1, tc := h0 -> first step sees h0 exactly.
    float tc = h0in[2*pair + u];
    float whOp[4], whXp[4];
#pragma unroll
    for (int q = 0; q < 4; q++) { whOp[q] = whO[q]; whXp[q] = whX[q]; }

    const float4* __restrict__ xr =
        reinterpret_cast<const float4*>(x) + (size_t)pair * (TT * 2 / 4);

    float4 buf[2][CHUNK / 2];
#pragma unroll
    for (int q = 0; q < CHUNK / 2; q++) buf[0][q] = __ldg(&xr[q]);

#pragma unroll 1
    for (int ch = 0; ch < TT / CHUNK; ch++) {
        const int nb = (ch + 1) & 1;
        if (ch + 1 < TT / CHUNK) {
#pragma unroll
            for (int q = 0; q < CHUNK / 2; q++)
                buf[nb][q] = __ldg(&xr[(ch + 1) * (CHUNK / 2) + q]);
        }
#pragma unroll
        for (int s2 = 0; s2 < CHUNK / 2; s2++) {
            const float4 v4 = buf[ch & 1][s2];
#pragma unroll
            for (int half = 0; half < 2; half++) {
                const float x0 = half ? v4.z : v4.x;
                const float x1 = half ? v4.w : v4.y;

                // Exchange tanh(c) — first op on the critical path.
                const float tc_oth = __shfl_xor_sync(0xffffffffu, tc, 1);

                // z_q: xpart (hoistable) + own tap (ready at tc+4) +
                // cross tap outermost (ready at shfl+4).
                float z[4];
#pragma unroll
                for (int q = 0; q < 4; q++) {
                    float t = fmaf(x1, wi1[q], bs[q]);
                    t = fmaf(x0, wi0[q], t);
                    t = fmaf(tc, whOp[q], t);
                    z[q] = fmaf(tc_oth, whXp[q], t);
                }

                // MUFU order: i, g, f on the c'-path in slots 0..2; o LAST
                // (its prep consumer has ~60 cyc slack under the next tanh(c)).
                const float ti = tanh_ap(z[0]);
                const float tg = tanh_ap(z[1]);
                const float tf = tanh_ap(z[2]);
                const float to = tanh_ap(z[3]);

                // c' = (0.5c)*t_f + (0.5c + sigma(i)*t_g), sigma = 0.5 t + 0.5
                const float si = fmaf(0.5f, ti, 0.5f);
                const float q0 = fmaf(si, tg, hc);
                c = fmaf(hc, tf, q0);

                tc = tanh_ap(c);     // critical path; prep hides under it

                // sigma_o + exchange + weight prep: all off-path (slack ~44+60).
                const float so     = fmaf(0.5f, to, 0.5f);
                const float so_oth = __shfl_xor_sync(0xffffffffu, so, 1);
#pragma unroll
                for (int q = 0; q < 4; q++) {
                    whOp[q] = whO[q] * so;
                    whXp[q] = whX[q] * so_oth;
                }
                hc = 0.5f * c;
            }
        }
    }

    out[2*pair + u] = c;
}

extern "C" void kernel_launch(void* const* d_in, const int* in_sizes, int n_in,
                              void* d_out, int out_size) {
    const float* x    = (const float*)d_in[0];
    const float* h0   = (const float*)d_in[1];
    const float* c0   = (const float*)d_in[2];
    const float* w_ih = (const float*)d_in[3];
    const float* w_hh = (const float*)d_in[4];
    const float* b_ih = (const float*)d_in[5];
    const float* b_hh = (const float*)d_in[6];
    lstm_kernel<<<NBLOCKS, NTHREADS>>>(x, h0, c0, w_ih, w_hh, b_ih, b_hh,
                                       (float*)d_out);
}

// round 14
// speedup vs baseline: 1.0885x; 1.0885x over previous
#include <cuda_runtime.h>

#define BB 8192
#define TT 2048
#define NTHREADS 128           // 4 warps/block -> 1 warp per SMSP
#define NBLOCKS  128           // 512 warps; lane pair per chain
#define CHUNK 8                // timesteps per prefetch chunk

__device__ __forceinline__ float tanh_ap(float x) {
    float y;
    asm("tanh.approx.f32 %0, %1;" : "=f"(y) : "f"(x));
    return y;
}

// R11 deferred-h lane-pair kernel + SOFTWARE-PIPELINED FILL:
// the next step's x-partials (8 FFMA) are computed inside the tanh(c) wait,
// after the sigma_o weight prep. This keeps the warp ISSUING through the
// MUFU wait so the dependent shfl doesn't pay the ~60cyc sleep/wakeup
// penalty (mechanism proven by R9's ILP-2: 149 cyc/step when filled).
// Gate/tanh order o,i,g,f (R11's — measured optimal; R12's o-last regressed).
__global__ void __launch_bounds__(NTHREADS, 1)
lstm_kernel(const float* __restrict__ x,
            const float* __restrict__ h0in,
            const float* __restrict__ c0in,
            const float* __restrict__ w_ih,
            const float* __restrict__ w_hh,
            const float* __restrict__ b_ih,
            const float* __restrict__ b_hh,
            float* __restrict__ out)
{
    const int tid  = blockIdx.x * NTHREADS + threadIdx.x;
    const int u    = tid & 1;           // hidden unit owned by this lane
    const int vv   = u ^ 1;             // partner's unit
    const int pair = tid >> 1;          // chain (batch element)

    // Gate order q: 0=o, 1=i, 2=g, 3=f (rows 6+u, 0+u, 4+u, 2+u).
    // sigma(z)=0.5*tanh(0.5z)+0.5 with 0.5 folded into weights/bias; g unscaled.
    float wi0[4], wi1[4], whO[4], whX[4], bs[4];
    const int qrow[4] = {6 + u, 0 + u, 4 + u, 2 + u};   // o, i, g, f
#pragma unroll
    for (int q = 0; q < 4; q++) {
        const int row = qrow[q];
        const float s = (q == 2) ? 1.0f : 0.5f;
        wi0[q] = s * __ldg(&w_ih[2*row+0]);
        wi1[q] = s * __ldg(&w_ih[2*row+1]);
        whO[q] = s * __ldg(&w_hh[2*row+u]);
        whX[q] = s * __ldg(&w_hh[2*row+vv]);
        bs[q]  = s * (__ldg(&b_ih[row]) + __ldg(&b_hh[row]));
    }

    float c  = c0in[2*pair + u];
    float hc = 0.5f * c;                // running 0.5*c (off critical path)

    // Deferred-h bootstrap: sigma_o := 1, tc := h0 -> first step sees h0 exactly.
    float tc = h0in[2*pair + u];
    float whOp[4], whXp[4];
#pragma unroll
    for (int q = 0; q < 4; q++) { whOp[q] = whO[q]; whXp[q] = whX[q]; }

    const float4* __restrict__ xr =
        reinterpret_cast<const float4*>(x) + (size_t)pair * (TT * 2 / 4);

    float4 buf[2][CHUNK / 2];
#pragma unroll
    for (int q = 0; q < CHUNK / 2; q++) buf[0][q] = __ldg(&xr[q]);

    // x-partials for step 0, pipelined one step ahead thereafter.
    float xp[4];
#pragma unroll
    for (int q = 0; q < 4; q++)
        xp[q] = fmaf(buf[0][0].x, wi0[q], fmaf(buf[0][0].y, wi1[q], bs[q]));

#pragma unroll 1
    for (int ch = 0; ch < TT / CHUNK; ch++) {
        const int cur = ch & 1;
        const int nb  = cur ^ 1;
        if (ch + 1 < TT / CHUNK) {
#pragma unroll
            for (int q = 0; q < CHUNK / 2; q++)
                buf[nb][q] = __ldg(&xr[(ch + 1) * (CHUNK / 2) + q]);
        }
#pragma unroll
        for (int s2 = 0; s2 < CHUNK / 2; s2++) {
            const float4 v4 = buf[cur][s2];
#pragma unroll
            for (int half = 0; half < 2; half++) {
                // x of the NEXT step (for the pipelined xpart in the fill
                // window). On the very last step these are stale/garbage but
                // the computed xp is never consumed.
                float nx0, nx1;
                if (half == 0)            { nx0 = v4.z;               nx1 = v4.w; }
                else if (s2 + 1 < CHUNK/2){ nx0 = buf[cur][s2+1].x;   nx1 = buf[cur][s2+1].y; }
                else                      { nx0 = buf[nb][0].x;       nx1 = buf[nb][0].y; }

                // ---- critical path ----
                const float tc_oth = __shfl_xor_sync(0xffffffffu, tc, 1);

                float z[4];
#pragma unroll
                for (int q = 0; q < 4; q++) {
                    float t = fmaf(tc, whOp[q], xp[q]);
                    z[q] = fmaf(tc_oth, whXp[q], t);
                }

                const float to = tanh_ap(z[0]);
                const float ti = tanh_ap(z[1]);
                const float tg = tanh_ap(z[2]);
                const float tf = tanh_ap(z[3]);

                const float so     = fmaf(0.5f, to, 0.5f);
                const float so_oth = __shfl_xor_sync(0xffffffffu, so, 1);

                const float si = fmaf(0.5f, ti, 0.5f);
                const float q0 = fmaf(si, tg, hc);
                c = fmaf(hc, tf, q0);

                tc = tanh_ap(c);     // ~60cyc wait -> fill window below

                // ---- fill window (keeps warp issuing; no sleep) ----
#pragma unroll
                for (int q = 0; q < 4; q++) {
                    whOp[q] = whO[q] * so;
                    whXp[q] = whX[q] * so_oth;
                }
                hc = 0.5f * c;
#pragma unroll
                for (int q = 0; q < 4; q++)
                    xp[q] = fmaf(nx0, wi0[q], fmaf(nx1, wi1[q], bs[q]));
            }
        }
    }

    out[2*pair + u] = c;
}

extern "C" void kernel_launch(void* const* d_in, const int* in_sizes, int n_in,
                              void* d_out, int out_size) {
    const float* x    = (const float*)d_in[0];
    const float* h0   = (const float*)d_in[1];
    const float* c0   = (const float*)d_in[2];
    const float* w_ih = (const float*)d_in[3];
    const float* w_hh = (const float*)d_in[4];
    const float* b_ih = (const float*)d_in[5];
    const float* b_hh = (const float*)d_in[6];
    lstm_kernel<<<NBLOCKS, NTHREADS>>>(x, h0, c0, w_ih, w_hh, b_ih, b_hh,
                                       (float*)d_out);
}